// round 4
// baseline (speedup 1.0000x reference)
#include <cuda_runtime.h>
#include <cstdint>

// ---------------------------------------------------------------------------
// TT embedding:  VOC = 100^3,  EMB = 4*4*8 = 128,  RANK = 16
//   out[tok, n1*32+n2*8+n3] = sum_{r1,r2} core0[i1,n1,r1]*core1[r1,i2,n2,r2]*core2[r2,i3,n3]
// idx = i1*10000 + i2*100 + i3; idx==0 (PAD) -> zero row.
//
// Kernel 1: G01[i12][n1*64 + n2*16 + r2] = sum_r1 core0*core1 (10.2MB, L2-resident)
// Kernel 2: warp/token. Coalesced G loads (2x LDG.128/lane); each lane
//           accumulates PARTIAL sums over the r2-half it owns, single
//           end-of-chain butterfly combines partials. Packed f32x2 FMA.
// ---------------------------------------------------------------------------

#define VOC_LL 1000000ULL

__device__ float g_G01[10000 * 256];

// ---- packed fp32x2 helpers (sm_103a) --------------------------------------
__device__ __forceinline__ unsigned long long f32x2_fma(
    unsigned long long a, unsigned long long b, unsigned long long c)
{
    unsigned long long d;
    asm("fma.rn.f32x2 %0, %1, %2, %3;" : "=l"(d) : "l"(a), "l"(b), "l"(c));
    return d;
}
__device__ __forceinline__ unsigned long long f32x2_add(
    unsigned long long a, unsigned long long b)
{
    unsigned long long d;
    asm("add.rn.f32x2 %0, %1, %2;" : "=l"(d) : "l"(a), "l"(b));
    return d;
}
__device__ __forceinline__ unsigned long long f32x2_bcast(float x)
{
    unsigned long long d;
    asm("mov.b64 %0, {%1, %1};" : "=l"(d) : "f"(x));
    return d;
}
__device__ __forceinline__ unsigned long long shfl_xor_u64(unsigned long long v, int m)
{
    unsigned int lo = (unsigned int)v, hi = (unsigned int)(v >> 32);
    lo = __shfl_xor_sync(0xffffffffu, lo, m);
    hi = __shfl_xor_sync(0xffffffffu, hi, m);
    return ((unsigned long long)hi << 32) | lo;
}

// ---------------------------------------------------------------------------
// Kernel 1: G01 precompute.  grid=(100 [i2], 20 [i1-group of 5]), block=128.
// core0: (1,100,4,16)  elem (i1,n1,r1)    @ i1*64 + n1*16 + r1
// core1: (16,100,4,16) elem (r1,i2,n2,r2) @ r1*6400 + i2*64 + n2*16 + r2
// ---------------------------------------------------------------------------
__global__ void __launch_bounds__(128) tt_precompute_g01(
    const float* __restrict__ core0,
    const float* __restrict__ core1)
{
    __shared__ float Bs[1024];   // core1 slice for this i2: [r1][n2*16+r2]
    __shared__ float As[320];    // core0 slices for 5 i1: [q][n1*16+r1]

    const int i2 = blockIdx.x;
    const int g  = blockIdx.y;   // i1 in [5g, 5g+5)
    const int p  = threadIdx.x;

    #pragma unroll
    for (int j = p; j < 1024; j += 128)
        Bs[j] = core1[(j >> 6) * 6400 + i2 * 64 + (j & 63)];
    #pragma unroll
    for (int j = p; j < 320; j += 128)
        As[j] = core0[g * 320 + j];
    __syncthreads();

    const int n1 = p >> 5;         // constant per warp -> As broadcast
    const int rp = (p & 31) * 2;   // rest pair start (n2*16+r2)

    unsigned long long b2[16];
    #pragma unroll
    for (int r1 = 0; r1 < 16; r1++)
        b2[r1] = *(const unsigned long long*)&Bs[r1 * 64 + rp];

    #pragma unroll
    for (int q = 0; q < 5; q++) {
        unsigned long long acc = 0;
        #pragma unroll
        for (int r1 = 0; r1 < 16; r1++)
            acc = f32x2_fma(f32x2_bcast(As[q * 64 + n1 * 16 + r1]), b2[r1], acc);
        const int i1 = g * 5 + q;
        *(unsigned long long*)&g_G01[((size_t)(i1 * 100 + i2)) * 256 + p * 2] = acc;
    }
}

// ---------------------------------------------------------------------------
// Kernel 2: gather.  1 warp per token, 4 outputs per lane.
// lane: row = lane>>1 (n1*4+n2), q = lane&1 (r2-half owned & n3-quad kept).
// G granule g (16B) = row*4 + c.  Lane L loads granules 2L, 2L+1 =
// gr[r2] for r2 in [8q, 8q+8) of its row (fully coalesced).
// Lane accumulates partials over its r2-half for ALL 8 n3 of the row;
// one end-of-chain butterfly (lane^1) merges the two halves.
// core2: (16,100,8,1) elem (r2,i3,n3) @ r2*800 + i3*8 + n3
// ---------------------------------------------------------------------------
__global__ void __launch_bounds__(256) tt_gather(
    const void*  __restrict__ xraw,
    const float* __restrict__ core2,
    float*       __restrict__ out,
    int n_tok)
{
    const int t    = threadIdx.x;
    const int lane = t & 31;
    const int tok  = blockIdx.x * 8 + (t >> 5);
    if (tok >= n_tok) return;

    // --- index dtype autodetect (int64 declared, but jax may emit int32) ---
    const unsigned long long* p64 = (const unsigned long long*)xraw;
    bool is64 = true;
    #pragma unroll
    for (int j = 0; j < 4; j++)
        if (p64[j] >= VOC_LL) is64 = false;

    const long long idxll = is64 ? ((const long long*)xraw)[tok]
                                 : (long long)((const int*)xraw)[tok];
    const unsigned int iv  = (unsigned int)idxll;      // < 1e6
    const unsigned int i3  = iv % 100u;
    const unsigned int i12 = iv / 100u;

    const int row = lane >> 1;   // n1*4 + n2
    const int q   = lane & 1;

    // own half of the G row: r2 in [8q, 8q+8)
    const float4* G = (const float4*)(g_G01 + (size_t)i12 * 256);
    const float4 ga = G[2 * lane];       // r2 = 8q+0..3
    const float4 gb = G[2 * lane + 1];   // r2 = 8q+4..7
    const float gr[8] = { ga.x, ga.y, ga.z, ga.w,  gb.x, gb.y, gb.z, gb.w };

    // partial sums over my r2-half for all 8 n3 of my row
    // acc0..acc3 = n3 {0,1},{2,3},{4,5},{6,7}
    const char* cbase = (const char*)core2 + (size_t)i3 * 32
                      + (size_t)q * 8 * 3200;
    unsigned long long acc0 = 0, acc1 = 0, acc2 = 0, acc3 = 0;
    #pragma unroll
    for (int k = 0; k < 8; k++) {
        const char* cp = cbase + (size_t)k * 3200;
        const ulonglong2 cA = *(const ulonglong2*)cp;          // n3 0..3
        const ulonglong2 cB = *(const ulonglong2*)(cp + 16);   // n3 4..7
        const unsigned long long gg = f32x2_bcast(gr[k]);
        acc0 = f32x2_fma(gg, cA.x, acc0);
        acc1 = f32x2_fma(gg, cA.y, acc1);
        acc2 = f32x2_fma(gg, cB.x, acc2);
        acc3 = f32x2_fma(gg, cB.y, acc3);
    }

    // single butterfly: keep n3 [4q,4q+4), send the other half to partner
    const unsigned long long keep0 = q ? acc2 : acc0;
    const unsigned long long keep1 = q ? acc3 : acc1;
    const unsigned long long send0 = q ? acc0 : acc2;
    const unsigned long long send1 = q ? acc1 : acc3;
    const unsigned long long recv0 = shfl_xor_u64(send0, 1);
    const unsigned long long recv1 = shfl_xor_u64(send1, 1);

    ulonglong2 res;
    res.x = f32x2_add(keep0, recv0);
    res.y = f32x2_add(keep1, recv1);
    if (iv == 0) { res.x = 0; res.y = 0; }   // PAD row
    *(ulonglong2*)(out + (size_t)tok * 128 + row * 8 + q * 4) = res;
}

// ---------------------------------------------------------------------------
extern "C" void kernel_launch(void* const* d_in, const int* in_sizes, int n_in,
                              void* d_out, int out_size)
{
    const void*  x     = d_in[0];
    const float* core0 = (const float*)d_in[1];
    const float* core1 = (const float*)d_in[2];
    const float* core2 = (const float*)d_in[3];
    float*       out   = (float*)d_out;

    const int n_tok = in_sizes[0];   // 32768

    tt_precompute_g01<<<dim3(100, 20), 128>>>(core0, core1);
    tt_gather<<<(n_tok + 7) / 8, 256>>>(x, core2, out, n_tok);
}

// round 5
// speedup vs baseline: 1.1987x; 1.1987x over previous
#include <cuda_runtime.h>
#include <cstdint>

// ---------------------------------------------------------------------------
// TT embedding:  VOC = 100^3,  EMB = 4*4*8 = 128,  RANK = 16
//   out[tok, n1*32+n2*8+n3] = sum_{r1,r2} core0[i1,n1,r1]*core1[r1,i2,n2,r2]*core2[r2,i3,n3]
// idx = i1*10000 + i2*100 + i3; idx==0 (PAD) -> zero row.
//
// Kernel 1: G01[i12][n1*64 + n2*16 + r2] = sum_r1 core0*core1 (10.2MB, L2-resident)
// Kernel 2: warp handles TWO tokens (independent chains for MLP), 4 outputs
//           per lane per token. R2-proven memory pattern: per-lane G row loads
//           (dedup'd across the lane pair), 16B broadcast C loads, packed
//           f32x2 FMA with r2-parity-split accumulator chains.
// ---------------------------------------------------------------------------

#define VOC_LL 1000000ULL

__device__ float g_G01[10000 * 256];

// ---- packed fp32x2 helpers (sm_103a) --------------------------------------
__device__ __forceinline__ unsigned long long f32x2_fma(
    unsigned long long a, unsigned long long b, unsigned long long c)
{
    unsigned long long d;
    asm("fma.rn.f32x2 %0, %1, %2, %3;" : "=l"(d) : "l"(a), "l"(b), "l"(c));
    return d;
}
__device__ __forceinline__ unsigned long long f32x2_add(
    unsigned long long a, unsigned long long b)
{
    unsigned long long d;
    asm("add.rn.f32x2 %0, %1, %2;" : "=l"(d) : "l"(a), "l"(b));
    return d;
}
__device__ __forceinline__ unsigned long long f32x2_bcast(float x)
{
    unsigned long long d;
    asm("mov.b64 %0, {%1, %1};" : "=l"(d) : "f"(x));
    return d;
}

// ---------------------------------------------------------------------------
// Kernel 1: G01 precompute.  grid=(100 [i2], 20 [i1-group of 5]), block=128.
// core0: (1,100,4,16)  elem (i1,n1,r1)    @ i1*64 + n1*16 + r1
// core1: (16,100,4,16) elem (r1,i2,n2,r2) @ r1*6400 + i2*64 + n2*16 + r2
// ---------------------------------------------------------------------------
__global__ void __launch_bounds__(128) tt_precompute_g01(
    const float* __restrict__ core0,
    const float* __restrict__ core1)
{
    __shared__ float Bs[1024];   // core1 slice for this i2: [r1][n2*16+r2]
    __shared__ float As[320];    // core0 slices for 5 i1: [q][n1*16+r1]

    const int i2 = blockIdx.x;
    const int g  = blockIdx.y;   // i1 in [5g, 5g+5)
    const int p  = threadIdx.x;

    #pragma unroll
    for (int j = p; j < 1024; j += 128)
        Bs[j] = core1[(j >> 6) * 6400 + i2 * 64 + (j & 63)];
    #pragma unroll
    for (int j = p; j < 320; j += 128)
        As[j] = core0[g * 320 + j];
    __syncthreads();

    const int n1 = p >> 5;         // constant per warp -> As broadcast
    const int rp = (p & 31) * 2;   // rest pair start (n2*16+r2)

    unsigned long long b2[16];
    #pragma unroll
    for (int r1 = 0; r1 < 16; r1++)
        b2[r1] = *(const unsigned long long*)&Bs[r1 * 64 + rp];

    #pragma unroll
    for (int q = 0; q < 5; q++) {
        unsigned long long acc = 0;
        #pragma unroll
        for (int r1 = 0; r1 < 16; r1++)
            acc = f32x2_fma(f32x2_bcast(As[q * 64 + n1 * 16 + r1]), b2[r1], acc);
        const int i1 = g * 5 + q;
        *(unsigned long long*)&g_G01[((size_t)(i1 * 100 + i2)) * 256 + p * 2] = acc;
    }
}

// ---------------------------------------------------------------------------
// Kernel 2: gather.  1 warp = 2 tokens, 4 outputs/lane/token.
// lane: row = lane>>1 (n1*4+n2), q = lane&1 (n3 quad).
// core2: (16,100,8,1) elem (r2,i3,n3) @ r2*800 + i3*8 + n3
// ---------------------------------------------------------------------------
__global__ void __launch_bounds__(256) tt_gather(
    const void*  __restrict__ xraw,
    const float* __restrict__ core2,
    float*       __restrict__ out,
    int n_tok)
{
    const int t    = threadIdx.x;
    const int lane = t & 31;
    const int tok0 = (blockIdx.x * 8 + (t >> 5)) * 2;
    const int tok1 = tok0 + 1;
    if (tok0 >= n_tok) return;

    // --- index dtype autodetect (int64 declared, but jax may emit int32) ---
    const unsigned long long* p64 = (const unsigned long long*)xraw;
    bool is64 = true;
    #pragma unroll
    for (int j = 0; j < 4; j++)
        if (p64[j] >= VOC_LL) is64 = false;

    const bool haveB = (tok1 < n_tok);
    const long long iA = is64 ? ((const long long*)xraw)[tok0]
                              : (long long)((const int*)xraw)[tok0];
    const long long iB = haveB ? (is64 ? ((const long long*)xraw)[tok1]
                                       : (long long)((const int*)xraw)[tok1])
                               : 0;
    const unsigned int ivA = (unsigned int)iA, ivB = (unsigned int)iB;  // < 1e6
    const unsigned int i3A = ivA % 100u, i12A = ivA / 100u;
    const unsigned int i3B = ivB % 100u, i12B = ivB / 100u;

    const int row = lane >> 1;   // n1*4 + n2
    const int q   = lane & 1;    // n3 in [4q, 4q+4)

    // G rows: 4 LDG.128 per token (lane pair dedups; 8 lines per instr)
    const float4* GA = (const float4*)(g_G01 + (size_t)i12A * 256) + row * 4;
    const float4* GB = (const float4*)(g_G01 + (size_t)i12B * 256) + row * 4;
    const float4 a0 = GA[0], a1 = GA[1], a2 = GA[2], a3 = GA[3];
    const float4 b0 = GB[0], b1 = GB[1], b2 = GB[2], b3 = GB[3];
    const float grA[16] = { a0.x,a0.y,a0.z,a0.w, a1.x,a1.y,a1.z,a1.w,
                            a2.x,a2.y,a2.z,a2.w, a3.x,a3.y,a3.z,a3.w };
    const float grB[16] = { b0.x,b0.y,b0.z,b0.w, b1.x,b1.y,b1.z,b1.w,
                            b2.x,b2.y,b2.z,b2.w, b3.x,b3.y,b3.z,b3.w };

    // C: per r2 one 16B broadcast load (one 32B sector per warp-instr)
    const char* cbA = (const char*)(core2 + (size_t)i3A * 8 + q * 4);
    const char* cbB = (const char*)(core2 + (size_t)i3B * 8 + q * 4);

    // r2-parity-split accumulator chains (depth 8 instead of 16)
    unsigned long long aA0e = 0, aA1e = 0, aA0o = 0, aA1o = 0;
    unsigned long long aB0e = 0, aB1e = 0, aB0o = 0, aB1o = 0;

    #pragma unroll
    for (int r2 = 0; r2 < 16; r2 += 2) {
        const ulonglong2 cAe = *(const ulonglong2*)(cbA + (size_t)r2 * 3200);
        const ulonglong2 cAo = *(const ulonglong2*)(cbA + (size_t)(r2 + 1) * 3200);
        const ulonglong2 cBe = *(const ulonglong2*)(cbB + (size_t)r2 * 3200);
        const ulonglong2 cBo = *(const ulonglong2*)(cbB + (size_t)(r2 + 1) * 3200);
        const unsigned long long gAe = f32x2_bcast(grA[r2]);
        const unsigned long long gAo = f32x2_bcast(grA[r2 + 1]);
        const unsigned long long gBe = f32x2_bcast(grB[r2]);
        const unsigned long long gBo = f32x2_bcast(grB[r2 + 1]);
        aA0e = f32x2_fma(gAe, cAe.x, aA0e);
        aA1e = f32x2_fma(gAe, cAe.y, aA1e);
        aA0o = f32x2_fma(gAo, cAo.x, aA0o);
        aA1o = f32x2_fma(gAo, cAo.y, aA1o);
        aB0e = f32x2_fma(gBe, cBe.x, aB0e);
        aB1e = f32x2_fma(gBe, cBe.y, aB1e);
        aB0o = f32x2_fma(gBo, cBo.x, aB0o);
        aB1o = f32x2_fma(gBo, cBo.y, aB1o);
    }

    ulonglong2 resA, resB;
    resA.x = f32x2_add(aA0e, aA0o);
    resA.y = f32x2_add(aA1e, aA1o);
    resB.x = f32x2_add(aB0e, aB0o);
    resB.y = f32x2_add(aB1e, aB1o);
    if (ivA == 0) { resA.x = 0; resA.y = 0; }   // PAD rows
    if (ivB == 0) { resB.x = 0; resB.y = 0; }

    const int off = row * 8 + q * 4;
    *(ulonglong2*)(out + (size_t)tok0 * 128 + off) = resA;
    if (haveB)
        *(ulonglong2*)(out + (size_t)tok1 * 128 + off) = resB;
}

// ---------------------------------------------------------------------------
extern "C" void kernel_launch(void* const* d_in, const int* in_sizes, int n_in,
                              void* d_out, int out_size)
{
    const void*  x     = d_in[0];
    const float* core0 = (const float*)d_in[1];
    const float* core1 = (const float*)d_in[2];
    const float* core2 = (const float*)d_in[3];
    float*       out   = (float*)d_out;

    const int n_tok = in_sizes[0];   // 32768

    tt_precompute_g01<<<dim3(100, 20), 128>>>(core0, core1);
    tt_gather<<<(n_tok + 15) / 16, 256>>>(x, core2, out, n_tok);
}